// round 17
// baseline (speedup 1.0000x reference)
#include <cuda_runtime.h>

// UniversalRNN: 2-layer tanh RNN (B=2048, T=512, IN=1, H=64) + FC(64->1).
// R16: R15 profile decomposition showed h-loads (each warp re-reading all 16
// rows, 4 crossbar phases each) + deg-2 bank conflicts as the L1 bottleneck.
// Retile: 16 warps = 2 row-groups x 8 dim-groups; tile 2r x 2d x 32k per
// thread (lane = 4rq x 4dq x 2kq). One shuffle round (kq exchange doubles as
// layer scatter: kq0 finalizes layer0, kq1 layer1). Bank-exact smem layout:
// pitch 84 (=20 mod 32), k-chunk1 at offset 48 (=16 mod 32), h1 buffer
// offset +16 words -> every LDS/STS instruction covers 32 distinct banks.

constexpr int Bq  = 2048;
constexpr int Tt  = 512;
constexpr int BBS = 16;   // row slots per CTA (padded)
constexpr int BBR = 14;   // real rows per CTA
constexpr int NT  = 512;  // threads per CTA (16 warps)
constexpr int HP  = 84;   // padded row pitch: 84 mod 32 = 20
constexpr int XS  = 65;   // x chunk row pitch
constexpr int HB  = BBS * HP;  // one h buffer = 1344 floats

// smem offsets (floats)
constexpr int OFF_W0  = 0;
constexpr int OFF_WI1 = OFF_W0 + 64 * HP;     // 5376
constexpr int OFF_WH1 = OFF_WI1 + 64 * HP;    // 10752
constexpr int OFF_H0  = OFF_WH1 + 64 * HP;    // 16128, [2][HB]
constexpr int OFF_H1  = OFF_H0 + 2 * HB + 16; // +16 pad: (H1-H0) mod 32 == 16
constexpr int OFF_XS  = OFF_H1 + 2 * HB;
constexpr int OFF_WFC = OFF_XS + BBS * XS;
constexpr int SMEM_FLOATS = OFF_WFC + 64;

// position of logical k/dim index c (0..63) within an 84-float padded row:
// k 0..31 at 0..31, k 32..63 at 48..79  (gap keeps kq1 chunk at 16 mod 32)
__device__ __host__ __forceinline__ int posmap(int c) { return c + 16 * (c >> 5); }

// tanh via ex2/rcp approx: ~1e-6 abs err
__device__ __forceinline__ float fast_tanhf(float x) {
    float e;
    asm("ex2.approx.f32 %0, %1;" : "=f"(e) : "f"(x * 2.8853900817779268f));
    float r;
    asm("rcp.approx.f32 %0, %1;" : "=f"(r) : "f"(e + 1.0f));
    return fmaf(-2.0f, r, 1.0f);
}

// packed 2xf32 fma (sm_100+ PTX only)
__device__ __forceinline__ unsigned long long fma2(
    unsigned long long a, unsigned long long b, unsigned long long c) {
    unsigned long long d;
    asm("fma.rn.f32x2 %0, %1, %2, %3;" : "=l"(d) : "l"(a), "l"(b), "l"(c));
    return d;
}

__device__ __forceinline__ float hsum2(unsigned long long v) {
    return __uint_as_float((unsigned)v) + __uint_as_float((unsigned)(v >> 32));
}

__global__ __launch_bounds__(NT, 1) void rnn_fused_kernel(
    const float* __restrict__ x,      // [B, T, 1]
    const float* __restrict__ Wih0,   // [64, 1]
    const float* __restrict__ Whh0,   // [64, 64]
    const float* __restrict__ bih0,   // [64]
    const float* __restrict__ bhh0,   // [64]
    const float* __restrict__ Wih1,   // [64, 64]
    const float* __restrict__ Whh1,   // [64, 64]
    const float* __restrict__ bih1,   // [64]
    const float* __restrict__ bhh1,   // [64]
    const float* __restrict__ Wfc,    // [1, 64]
    const float* __restrict__ bfc,    // [1]
    float* __restrict__ out)          // [B, 1]
{
    extern __shared__ float sm[];
    float* W0  = sm + OFF_W0;
    float* Wi1 = sm + OFF_WI1;
    float* Wh1 = sm + OFF_WH1;
    float* h0s = sm + OFF_H0;
    float* h1s = sm + OFF_H1;
    float* xs  = sm + OFF_XS;
    float* wfc = sm + OFF_WFC;

    const int tx = threadIdx.x;
    const int b0 = blockIdx.x * BBR;

    // ---- stage weights with gap layout ----
    for (int idx = tx; idx < 64 * 64; idx += NT) {
        int r = idx >> 6, c = idx & 63;
        int pc = posmap(c);
        W0 [r * HP + pc] = Whh0[idx];
        Wi1[r * HP + pc] = Wih1[idx];
        Wh1[r * HP + pc] = Whh1[idx];
    }
    if (tx < 64) wfc[tx] = Wfc[tx];
    // zero both h regions (covers pad too)
    for (int idx = tx; idx < 4 * HB + 16; idx += NT)
        sm[OFF_H0 + idx] = 0.0f;

    // warp w: rg = w>>3 (row group), dg = w&7 (dim group).
    // lane = kq*16 + dq*4 + rq: kq 0..1 (k-half / final phase),
    // dq 0..3 (dims da=8dg+dq, db=da+4), rq 0..3 (rows r0=rg*8+rq, r1=r0+4)
    const int wrp  = tx >> 5;
    const int lane = tx & 31;
    const int rg = wrp >> 3, dg = wrp & 7;
    const int kq = lane >> 4;
    const int dq = (lane >> 2) & 3;
    const int rq = lane & 3;
    const int r0 = rg * 8 + rq, r1 = r0 + 4;
    const int da = 8 * dg + dq, db = da + 4;
    const int pa = posmap(da), pb = posmap(db);
    const int ko0 = 48 * kq;          // k-chunk base position
    const bool p = (kq != 0);         // this lane finalizes layer1

    const float wxa = Wih0[da], wxb = Wih0[db];
    const float b0a = bih0[da] + bhh0[da];
    const float b0b = bih0[db] + bhh0[db];
    const float b1a = bih1[da] + bhh1[da];
    const float b1b = bih1[db] + bhh1[db];

    __syncthreads();

    int cur = 0;
    // interval i: phaseA computes h0(i) (i<Tt), phaseB computes h1(i-1) (i>=1)
    for (int i = 0; i <= Tt; ++i) {
        if ((i & 63) == 0 && i < Tt) {
            #pragma unroll
            for (int j = 0; j < (BBS * 64) / NT; ++j) {
                int idx = tx + j * NT;
                int r = idx >> 6, c = idx & 63;
                float v = 0.0f;
                if (r < BBR) v = x[(b0 + r) * Tt + i + c];
                xs[r * XS + c] = v;
            }
            __syncthreads();
        }
        const int tc = i & 63;
        const float* h0c = h0s + cur * HB;        // h0(i-1)
        float*       h0n = h0s + (cur ^ 1) * HB;  // h0(i)
        const float* h1c = h1s + cur * HB;        // h1(i-2)
        float*       h1n = h1s + (cur ^ 1) * HB;  // h1(i-1)

        unsigned long long A00 = 0, A01 = 0, A10 = 0, A11 = 0;
        unsigned long long B00 = 0, B01 = 0, B10 = 0, B11 = 0;

        #pragma unroll
        for (int ii = 0; ii < 8; ++ii) {
            const int ko = ko0 + 4 * ii;
            ulonglong2 g0 = *(const ulonglong2*)(h0c + r0 * HP + ko);
            ulonglong2 g1 = *(const ulonglong2*)(h0c + r1 * HP + ko);
            ulonglong2 wa = *(const ulonglong2*)(W0 + da * HP + ko);
            ulonglong2 wb = *(const ulonglong2*)(W0 + db * HP + ko);
            A00 = fma2(g0.x, wa.x, A00); A00 = fma2(g0.y, wa.y, A00);
            A01 = fma2(g0.x, wb.x, A01); A01 = fma2(g0.y, wb.y, A01);
            A10 = fma2(g1.x, wa.x, A10); A10 = fma2(g1.y, wa.y, A10);
            A11 = fma2(g1.x, wb.x, A11); A11 = fma2(g1.y, wb.y, A11);

            ulonglong2 ia = *(const ulonglong2*)(Wi1 + da * HP + ko);
            ulonglong2 ib = *(const ulonglong2*)(Wi1 + db * HP + ko);
            B00 = fma2(g0.x, ia.x, B00); B00 = fma2(g0.y, ia.y, B00);
            B01 = fma2(g0.x, ib.x, B01); B01 = fma2(g0.y, ib.y, B01);
            B10 = fma2(g1.x, ia.x, B10); B10 = fma2(g1.y, ia.y, B10);
            B11 = fma2(g1.x, ib.x, B11); B11 = fma2(g1.y, ib.y, B11);

            ulonglong2 q0 = *(const ulonglong2*)(h1c + r0 * HP + ko);
            ulonglong2 q1 = *(const ulonglong2*)(h1c + r1 * HP + ko);
            ulonglong2 ha = *(const ulonglong2*)(Wh1 + da * HP + ko);
            ulonglong2 hb = *(const ulonglong2*)(Wh1 + db * HP + ko);
            B00 = fma2(q0.x, ha.x, B00); B00 = fma2(q0.y, ha.y, B00);
            B01 = fma2(q0.x, hb.x, B01); B01 = fma2(q0.y, hb.y, B01);
            B10 = fma2(q1.x, ha.x, B10); B10 = fma2(q1.y, ha.y, B10);
            B11 = fma2(q1.x, hb.x, B11); B11 = fma2(q1.y, hb.y, B11);
        }

        // ---- single exchange round: kq0<->kq1 swap. kq0 keeps A (layer0),
        // kq1 keeps B (layer1); each sends the other phase's partial.
        float sA[4], sB[4], tot[4];
        sA[0] = hsum2(A00); sA[1] = hsum2(A01); sA[2] = hsum2(A10); sA[3] = hsum2(A11);
        sB[0] = hsum2(B00); sB[1] = hsum2(B01); sB[2] = hsum2(B10); sB[3] = hsum2(B11);
        #pragma unroll
        for (int m = 0; m < 4; ++m) {
            float send = p ? sA[m] : sB[m];
            float recv = __shfl_xor_sync(0xffffffffu, send, 16);
            tot[m] = (p ? sB[m] : sA[m]) + recv;
        }

        // ---- finalize: kq0 -> h0(i) (x-inject + tanh), kq1 -> h1(i-1)
        {
            const float xv0 = xs[r0 * XS + tc];
            const float xv1 = xs[r1 * XS + tc];
            float a0 = p ? (tot[0] + b1a) : fmaf(xv0, wxa, tot[0] + b0a);
            float a1 = p ? (tot[1] + b1b) : fmaf(xv0, wxb, tot[1] + b0b);
            float a2 = p ? (tot[2] + b1a) : fmaf(xv1, wxa, tot[2] + b0a);
            float a3 = p ? (tot[3] + b1b) : fmaf(xv1, wxb, tot[3] + b0b);
            float t0 = fast_tanhf(a0);
            float t1 = fast_tanhf(a1);
            float t2 = fast_tanhf(a2);
            float t3 = fast_tanhf(a3);
            float* dst = p ? h1n : h0n;
            if (!p || i != 0) {
                dst[r0 * HP + pa] = t0;
                dst[r0 * HP + pb] = t1;
                dst[r1 * HP + pa] = t2;
                dst[r1 * HP + pb] = t3;
            }
        }
        __syncthreads();
        cur ^= 1;
    }

    // ---- FC head: out[b] = Wfc . h1(Tt-1)[b] + bfc ----
    const float* h1f = h1s + cur * HB;
    if (tx < BBR) {
        float acc = bfc[0];
        #pragma unroll
        for (int k = 0; k < 64; ++k)
            acc = fmaf(h1f[tx * HP + posmap(k)], wfc[k], acc);
        out[b0 + tx] = acc;
    }
}

extern "C" void kernel_launch(void* const* d_in, const int* in_sizes, int n_in,
                              void* d_out, int out_size) {
    (void)in_sizes; (void)n_in; (void)out_size;
    const float* x    = (const float*)d_in[0];
    const float* Wih0 = (const float*)d_in[1];
    const float* Whh0 = (const float*)d_in[2];
    const float* bih0 = (const float*)d_in[3];
    const float* bhh0 = (const float*)d_in[4];
    const float* Wih1 = (const float*)d_in[5];
    const float* Whh1 = (const float*)d_in[6];
    const float* bih1 = (const float*)d_in[7];
    const float* bhh1 = (const float*)d_in[8];
    const float* Wfc  = (const float*)d_in[9];
    const float* bfc  = (const float*)d_in[10];
    float* out = (float*)d_out;

    constexpr int SMEM_BYTES = SMEM_FLOATS * 4;  // ~90.5 KB

    cudaFuncSetAttribute(rnn_fused_kernel,
                         cudaFuncAttributeMaxDynamicSharedMemorySize, SMEM_BYTES);

    constexpr int GRID = (Bq + BBR - 1) / BBR;  // 147 CTAs -> all SMs
    rnn_fused_kernel<<<GRID, NT, SMEM_BYTES>>>(
        x, Wih0, Whh0, bih0, bhh0, Wih1, Whh1, bih1, bhh1, Wfc, bfc, out);
}